// round 5
// baseline (speedup 1.0000x reference)
#include <cuda_runtime.h>
#include <cstdint>
#include <cstddef>

#define TT 16
#define HEADS 8
#define DH 40
#define CC 320
#define SPATIAL 1024
#define NSLAB 64
#define SLAB (CC * SPATIAL)

// Scratch: Q, K, V, O buffers [64][320][1024] fp32, then 4 rounded W matrices
__device__ float g_scratch[4ull * NSLAB * SLAB + 4ull * CC * CC];

// ================= helpers =================
__device__ __forceinline__ uint32_t smem_u32(const void* p) {
    uint32_t a;
    asm("{ .reg .u64 t; cvta.to.shared.u64 t, %1; cvt.u32.u64 %0, t; }"
        : "=r"(a) : "l"(p));
    return a;
}
__device__ __forceinline__ void ldsm4(uint32_t& r0, uint32_t& r1, uint32_t& r2,
                                      uint32_t& r3, uint32_t a) {
    asm volatile("ldmatrix.sync.aligned.m8n8.x4.shared.b16 {%0,%1,%2,%3}, [%4];"
                 : "=r"(r0), "=r"(r1), "=r"(r2), "=r"(r3) : "r"(a));
}
__device__ __forceinline__ uint32_t lds32(uint32_t a) {
    uint32_t v;
    asm volatile("ld.shared.b32 %0, [%1];" : "=r"(v) : "r"(a));
    return v;
}
__device__ __forceinline__ void mma8(float* c, const uint32_t* a,
                                     uint32_t b0, uint32_t b1) {
    asm volatile(
        "mma.sync.aligned.m16n8k8.row.col.f32.tf32.tf32.f32 "
        "{%0,%1,%2,%3},{%4,%5,%6,%7},{%8,%9},{%0,%1,%2,%3};"
        : "+f"(c[0]), "+f"(c[1]), "+f"(c[2]), "+f"(c[3])
        : "r"(a[0]), "r"(a[1]), "r"(a[2]), "r"(a[3]), "r"(b0), "r"(b1));
}
#define CP_ASYNC(dst, src, sz) \
    asm volatile("cp.async.cg.shared.global [%0], [%1], 16, %2;" \
                 :: "r"(dst), "l"(src), "r"(sz))
#define CP_COMMIT() asm volatile("cp.async.commit_group;" ::: "memory")

// ================= GEMM =================
// C[m0:+128, n0:+128] = W[320,320] @ X[320,1024], K=320 (10 tiles of 32).
// 256 thr = 8 warps (2m x 4n), warp tile 64x32, tf32 mma.sync, fp32 accum.
// 3-stage cp.async pipeline. Stage: A [128][36] fl (18432B) + B [32][136] fl
// (17408B) = 35840B; x3 = 107520B dynamic smem.
template <bool EPI>
__device__ __forceinline__ void tc_gemm(
    const float* __restrict__ W, const float* __restrict__ X,
    float* __restrict__ C, const float* __restrict__ bias,
    const float* __restrict__ R, int m0, int n0)
{
    extern __shared__ float smem[];
    const int tid = threadIdx.x;
    const int lane = tid & 31, wid = tid >> 5;
    const int wm = (wid & 1) * 64, wn = (wid >> 1) * 32;
    const uint32_t sb = smem_u32(smem);

    float c[4][4][4];
#pragma unroll
    for (int a = 0; a < 4; a++)
#pragma unroll
        for (int b = 0; b < 4; b++)
#pragma unroll
            for (int d = 0; d < 4; d++) c[a][b][d] = 0.f;

    auto stage = [&](int i) {
        const int kt = i * 32;
        const uint32_t as = sb + (uint32_t)(i % 3) * 35840u;
        const uint32_t bs = as + 18432u;
#pragma unroll
        for (int t = 0; t < 4; t++) {
            const int idx = t * 256 + tid;
            const int row = idx >> 3, ch = idx & 7;
            const float* src = W + (size_t)(m0 + row) * CC + kt + ch * 4;
            const int sz = (m0 + row < CC) ? 16 : 0;
            CP_ASYNC(as + (uint32_t)(row * 144 + ch * 16), src, sz);
        }
#pragma unroll
        for (int t = 0; t < 4; t++) {
            const int idx = t * 256 + tid;
            const int k = idx >> 5, nc = idx & 31;
            const float* src = X + (size_t)(kt + k) * SPATIAL + n0 + nc * 4;
            CP_ASYNC(bs + (uint32_t)(k * 544 + nc * 16), src, 16);
        }
        CP_COMMIT();
    };

    stage(0);
    stage(1);

    for (int i = 0; i < 10; i++) {
        if (i == 9) asm volatile("cp.async.wait_group 0;" ::: "memory");
        else        asm volatile("cp.async.wait_group 1;" ::: "memory");
        __syncthreads();

        const uint32_t as = sb + (uint32_t)(i % 3) * 35840u;
        const uint32_t bs = as + 18432u;

#pragma unroll
        for (int s = 0; s < 4; s++) {
            uint32_t af[4][4];
#pragma unroll
            for (int mt = 0; mt < 4; mt++) {
                const uint32_t addr = as +
                    (uint32_t)((wm + mt * 16 + (lane & 15)) * 144 +
                               s * 32 + ((lane >> 4) * 16));
                ldsm4(af[mt][0], af[mt][1], af[mt][2], af[mt][3], addr);
            }
#pragma unroll
            for (int nt = 0; nt < 4; nt++) {
                const uint32_t ba = bs +
                    (uint32_t)(((s * 8 + (lane & 3)) * 136 +
                                wn + nt * 8 + (lane >> 2)) * 4);
                const uint32_t b0 = lds32(ba);
                const uint32_t b1 = lds32(ba + 4 * 136 * 4);
#pragma unroll
                for (int mt = 0; mt < 4; mt++)
                    mma8(c[mt][nt], af[mt], b0, b1);
            }
        }
        __syncthreads();
        if (i + 2 < 10) stage(i + 2);
    }

    // ---- epilogue: direct register -> STG (float2 pairs) ----
#pragma unroll
    for (int mt = 0; mt < 4; mt++) {
#pragma unroll
        for (int nt = 0; nt < 4; nt++) {
            const int r0 = m0 + wm + mt * 16 + (lane >> 2);
            const int col = n0 + wn + nt * 8 + (lane & 3) * 2;
            if (r0 < CC) {
                const size_t o0 = (size_t)r0 * SPATIAL + col;
                float v0 = c[mt][nt][0], v1 = c[mt][nt][1];
                if (EPI) {
                    const float bb = bias[r0];
                    const float2 x0 = *(const float2*)(R + o0);
                    v0 += bb + x0.x; v1 += bb + x0.y;
                }
                *(float2*)(C + o0) = make_float2(v0, v1);
            }
            if (r0 + 8 < CC) {
                const size_t o1 = (size_t)(r0 + 8) * SPATIAL + col;
                float v2 = c[mt][nt][2], v3 = c[mt][nt][3];
                if (EPI) {
                    const float bb = bias[r0 + 8];
                    const float2 x1 = *(const float2*)(R + o1);
                    v2 += bb + x1.x; v3 += bb + x1.y;
                }
                *(float2*)(C + o1) = make_float2(v2, v3);
            }
        }
    }
}

__global__ __launch_bounds__(256, 2) void qkv_tc(
    const float* __restrict__ Wr, const float* __restrict__ X,
    float* __restrict__ out)
{
    const int slab = blockIdx.z;
    const int wsel = blockIdx.y / 3, mt = blockIdx.y % 3;
    tc_gemm<false>(Wr + (size_t)wsel * CC * CC, X + (size_t)slab * SLAB,
                   out + (size_t)wsel * NSLAB * SLAB + (size_t)slab * SLAB,
                   nullptr, nullptr, mt * 128, blockIdx.x * 128);
}

__global__ __launch_bounds__(256, 2) void o_tc(
    const float* __restrict__ Wr, const float* __restrict__ O,
    const float* __restrict__ bo, const float* __restrict__ X,
    float* __restrict__ out)
{
    const int slab = blockIdx.z;
    tc_gemm<true>(Wr + 3ull * CC * CC, O + (size_t)slab * SLAB,
                  out + (size_t)slab * SLAB, bo, X + (size_t)slab * SLAB,
                  blockIdx.y * 128, blockIdx.x * 128);
}

// ---- W pre-round (RNA -> tf32 bits in fp32 container) ----
__global__ void round_w(const float* __restrict__ Wq, const float* __restrict__ Wk,
                        const float* __restrict__ Wv, const float* __restrict__ Wo,
                        float* __restrict__ dst)
{
    const int z = blockIdx.y;
    const int i = blockIdx.x * 1024 + threadIdx.x;  // < 102400
    const float* s = (z == 0) ? Wq : (z == 1) ? Wk : (z == 2) ? Wv : Wo;
    float v = s[i];
    asm("cvt.rna.tf32.f32 %0, %1;" : "=f"(v) : "f"(v));
    dst[(size_t)z * CC * CC + i] = v;
}

// ================= Attention =================
// Block = (b, h, 32 spatial). 256 thr = 8 warps; warp tg does t=tg, then
// t=15-tg (balanced). V + rel tables staged in smem (92.5KB -> 2 CTAs/SM);
// K read from global (L1-cached, ~8.5x block-level reuse).
__global__ __launch_bounds__(256, 2) void attn_kernel(
    const float* __restrict__ Qg, const float* __restrict__ Kg,
    const float* __restrict__ Vg, float* __restrict__ Og,
    const float* __restrict__ relk, const float* __restrict__ relv)
{
    extern __shared__ float sm[];
    float* Vs = sm;              // 16*40*32 = 20480
    float* Rk = sm + 20480;      // 1320
    float* Rv = sm + 21800;      // 1320  (total 23120 fl = 92480 B)

    const int b = blockIdx.z;
    const int h = blockIdx.y;
    const int s0 = blockIdx.x * 32;
    const int tid = threadIdx.x;

    for (int i = tid; i < TT * DH * 32; i += 256) {
        const int row = i >> 5, sl2 = i & 31;
        const int f = row / DH, dd = row - f * DH;
        Vs[i] = Vg[((size_t)((b * TT + f) * CC + h * DH + dd)) * SPATIAL + s0 + sl2];
    }
    for (int i = tid; i < 33 * DH; i += 256) {
        Rk[i] = relk[i];
        Rv[i] = relv[i];
    }
    __syncthreads();

    const int sl = tid & 31;
    const int tg = tid >> 5;
    const float scale = 0.15811388300841898f;  // 40^-0.5
    const size_t kb = ((size_t)(b * TT * CC + h * DH)) * SPATIAL + s0 + sl;

    for (int rep = 0; rep < 2; rep++) {
        const int t = rep ? (15 - tg) : tg;  // warp-uniform
        const size_t base = kb + (size_t)t * CC * SPATIAL;

        float q[DH];
#pragma unroll
        for (int dd = 0; dd < DH; dd++) q[dd] = Qg[base + (size_t)dd * SPATIAL];

        float sim[TT];
        float mx = -1e30f;
#pragma unroll
        for (int sp = 0; sp < TT; sp++) {
            if (sp > t) break;               // warp-uniform
            const float* kp = Kg + kb + (size_t)sp * CC * SPATIAL;
            const float* rp = Rk + (sp - t + TT) * DH;
            float acc = 0.f;
#pragma unroll
            for (int dd = 0; dd < DH; dd++)
                acc += q[dd] * (kp[(size_t)dd * SPATIAL] + rp[dd]);
            acc *= scale;
            sim[sp] = acc;
            mx = fmaxf(mx, acc);
        }
        float den = 0.f;
#pragma unroll
        for (int sp = 0; sp < TT; sp++) {
            if (sp > t) break;
            const float e = __expf(sim[sp] - mx);
            sim[sp] = e;
            den += e;
        }
        const float inv = 1.f / den;

        float o[DH];
#pragma unroll
        for (int dd = 0; dd < DH; dd++) o[dd] = 0.f;
#pragma unroll
        for (int sp = 0; sp < TT; sp++) {
            if (sp > t) break;
            const float a = sim[sp];
            const float* vp = Vs + (sp * DH) * 32 + sl;
            const float* rp = Rv + (sp - t + TT) * DH;
#pragma unroll
            for (int dd = 0; dd < DH; dd++) o[dd] += a * (vp[dd * 32] + rp[dd]);
        }
#pragma unroll
        for (int dd = 0; dd < DH; dd++)
            Og[base + (size_t)dd * SPATIAL] = o[dd] * inv;
    }
}

// ================= launch =================
extern "C" void kernel_launch(void* const* d_in, const int* in_sizes, int n_in,
                              void* d_out, int out_size) {
    const float* x  = (const float*)d_in[0];
    const float* Wq = (const float*)d_in[1];
    const float* Wk = (const float*)d_in[2];
    const float* Wv = (const float*)d_in[3];
    const float* Wo = (const float*)d_in[4];
    const float* bo = (const float*)d_in[5];
    const float* rk = (const float*)d_in[6];
    const float* rv = (const float*)d_in[7];
    float* out = (float*)d_out;

    float* sc = nullptr;
    cudaGetSymbolAddress((void**)&sc, g_scratch);
    float* Q  = sc;
    float* K  = sc + 1ull * NSLAB * SLAB;
    float* V  = sc + 2ull * NSLAB * SLAB;
    float* O  = sc + 3ull * NSLAB * SLAB;
    float* Wr = sc + 4ull * NSLAB * SLAB;

    round_w<<<dim3(100, 4), 1024>>>(Wq, Wk, Wv, Wo, Wr);

    const int gsm = 107520;
    cudaFuncSetAttribute((const void*)qkv_tc,
                         cudaFuncAttributeMaxDynamicSharedMemorySize, gsm);
    cudaFuncSetAttribute((const void*)o_tc,
                         cudaFuncAttributeMaxDynamicSharedMemorySize, gsm);

    qkv_tc<<<dim3(SPATIAL / 128, 9, NSLAB), 256, gsm>>>(Wr, x, sc);

    const int asm_b = 23120 * 4;
    cudaFuncSetAttribute((const void*)attn_kernel,
                         cudaFuncAttributeMaxDynamicSharedMemorySize, asm_b);
    attn_kernel<<<dim3(SPATIAL / 32, HEADS, 4), 256, asm_b>>>(Q, K, V, O, rk, rv);

    o_tc<<<dim3(SPATIAL / 128, 3, NSLAB), 256, gsm>>>(Wr, O, bo, x, out);
}

// round 6
// speedup vs baseline: 1.7534x; 1.7534x over previous
#include <cuda_runtime.h>
#include <cuda_fp16.h>
#include <cstdint>
#include <cstddef>

#define TT 16
#define HEADS 8
#define DH 40
#define CC 320
#define SPATIAL 1024
#define NSLAB 64
#define SLAB (CC * SPATIAL)
#define NELEM (1ull * NSLAB * SLAB)   // 20,971,520

// fp16 scratch: Q,K,V,O, Xh (5 x NELEM) + 4 converted W matrices
__device__ __half g_hbuf[5ull * NELEM + 4ull * CC * CC];

// ================= helpers =================
__device__ __forceinline__ uint32_t smem_u32(const void* p) {
    uint32_t a;
    asm("{ .reg .u64 t; cvta.to.shared.u64 t, %1; cvt.u32.u64 %0, t; }"
        : "=r"(a) : "l"(p));
    return a;
}
__device__ __forceinline__ void ldsm4(uint32_t* r, uint32_t a) {
    asm volatile("ldmatrix.sync.aligned.m8n8.x4.shared.b16 {%0,%1,%2,%3}, [%4];"
                 : "=r"(r[0]), "=r"(r[1]), "=r"(r[2]), "=r"(r[3]) : "r"(a));
}
__device__ __forceinline__ void ldsm4t(uint32_t* r, uint32_t a) {
    asm volatile("ldmatrix.sync.aligned.m8n8.x4.trans.shared.b16 {%0,%1,%2,%3}, [%4];"
                 : "=r"(r[0]), "=r"(r[1]), "=r"(r[2]), "=r"(r[3]) : "r"(a));
}
__device__ __forceinline__ void mma16(float* c, const uint32_t* a,
                                      uint32_t b0, uint32_t b1) {
    asm volatile(
        "mma.sync.aligned.m16n8k16.row.col.f32.f16.f16.f32 "
        "{%0,%1,%2,%3},{%4,%5,%6,%7},{%8,%9},{%0,%1,%2,%3};"
        : "+f"(c[0]), "+f"(c[1]), "+f"(c[2]), "+f"(c[3])
        : "r"(a[0]), "r"(a[1]), "r"(a[2]), "r"(a[3]), "r"(b0), "r"(b1));
}
#define CP_ASYNC(dst, src, sz) \
    asm volatile("cp.async.cg.shared.global [%0], [%1], 16, %2;" \
                 :: "r"(dst), "l"(src), "r"(sz))
#define CP_COMMIT() asm volatile("cp.async.commit_group;" ::: "memory")

// ================= conversion kernels =================
__global__ __launch_bounds__(256) void cvt_x(const float* __restrict__ x,
                                             __half* __restrict__ xh) {
    const size_t i = ((size_t)blockIdx.x * 256 + threadIdx.x) * 8;
    float4 a = *(const float4*)(x + i);
    float4 b = *(const float4*)(x + i + 4);
    __half2 h[4] = { __floats2half2_rn(a.x, a.y), __floats2half2_rn(a.z, a.w),
                     __floats2half2_rn(b.x, b.y), __floats2half2_rn(b.z, b.w) };
    *(uint4*)(xh + i) = *(uint4*)h;
}
__global__ void cvt_w(const float* __restrict__ Wq, const float* __restrict__ Wk,
                      const float* __restrict__ Wv, const float* __restrict__ Wo,
                      __half* __restrict__ dst) {
    const int z = blockIdx.y;
    const int i = blockIdx.x * 1024 + threadIdx.x;   // < 102400
    const float* s = (z == 0) ? Wq : (z == 1) ? Wk : (z == 2) ? Wv : Wo;
    dst[(size_t)z * CC * CC + i] = __float2half_rn(s[i]);
}

// ================= fp16 tensor-core GEMM =================
// C[m0:+128, n0:+128] = W[320,320] @ X[320,1024] (K=320, 10 tiles of BK=32)
// 8 warps (2m x 4n), warp tile 64x32, mma.m16n8k16, fp32 accum.
// A stage: 128 rows x pitch 40 halves (80B) = 10240B (conflict-free ldsm)
// B stage: 32 rows  x pitch 136 halves (272B) = 8704B (conflict-free ldsm.trans)
// 3 stages x 18944B = 56832B dynamic smem.
#define APITCH 40
#define BPITCH 136
#define STAGEB 18944

template <bool EPI>
__device__ __forceinline__ void tc_gemm(
    const __half* __restrict__ W, const __half* __restrict__ X,
    void* __restrict__ Cout, const float* __restrict__ bias,
    const float* __restrict__ R, int m0, int n0)
{
    extern __shared__ char smem[];
    const int tid = threadIdx.x;
    const int lane = tid & 31, wid = tid >> 5;
    const int wm = (wid & 1) * 64, wn = (wid >> 1) * 32;
    const uint32_t sb = smem_u32(smem);

    float c[4][4][4];
#pragma unroll
    for (int a = 0; a < 4; a++)
#pragma unroll
        for (int b = 0; b < 4; b++)
#pragma unroll
            for (int d = 0; d < 4; d++) c[a][b][d] = 0.f;

    auto stage = [&](int i) {
        const int kt = i * 32;
        const uint32_t as = sb + (uint32_t)(i % 3) * STAGEB;
        const uint32_t bs = as + 10240u;
        // A: 128 rows x 32 halves = 512 x 16B
#pragma unroll
        for (int t = 0; t < 2; t++) {
            const int idx = t * 256 + tid;
            const int row = idx >> 2, ch = idx & 3;
            const __half* src = W + (size_t)(m0 + row) * CC + kt + ch * 8;
            const int sz = (m0 + row < CC) ? 16 : 0;
            CP_ASYNC(as + (uint32_t)(row * (APITCH * 2) + ch * 16), src, sz);
        }
        // B: 32 rows x 128 halves = 512 x 16B
#pragma unroll
        for (int t = 0; t < 2; t++) {
            const int idx = t * 256 + tid;
            const int k = idx >> 4, nc = idx & 15;
            const __half* src = X + (size_t)(kt + k) * SPATIAL + n0 + nc * 8;
            CP_ASYNC(bs + (uint32_t)(k * (BPITCH * 2) + nc * 16), src, 16);
        }
        CP_COMMIT();
    };

    stage(0);
    stage(1);

    for (int i = 0; i < 10; i++) {
        if (i < 8) asm volatile("cp.async.wait_group 1;" ::: "memory");
        else       asm volatile("cp.async.wait_group 0;" ::: "memory");
        __syncthreads();
        if (i + 2 < 10) stage(i + 2);

        const uint32_t as = sb + (uint32_t)(i % 3) * STAGEB;
        const uint32_t bs = as + 10240u;

#pragma unroll
        for (int ks = 0; ks < 2; ks++) {
            uint32_t af[4][4], bf[2][4];
#pragma unroll
            for (int mt = 0; mt < 4; mt++) {
                const uint32_t addr = as +
                    (uint32_t)((wm + mt * 16 + (lane & 15)) * (APITCH * 2) +
                               (lane >> 4) * 16 + ks * 32);
                ldsm4(af[mt], addr);
            }
#pragma unroll
            for (int nb = 0; nb < 2; nb++) {
                const uint32_t addr = bs +
                    (uint32_t)((ks * 16 + (lane & 15)) * (BPITCH * 2) +
                               (wn + nb * 16 + (lane >> 4) * 8) * 2);
                ldsm4t(bf[nb], addr);
            }
#pragma unroll
            for (int nt = 0; nt < 4; nt++) {
                const uint32_t b0 = bf[nt >> 1][(nt & 1) * 2];
                const uint32_t b1 = bf[nt >> 1][(nt & 1) * 2 + 1];
#pragma unroll
                for (int mt = 0; mt < 4; mt++)
                    mma16(c[mt][nt], af[mt], b0, b1);
            }
        }
        __syncthreads();
    }

    // ---- epilogue ----
#pragma unroll
    for (int mt = 0; mt < 4; mt++) {
#pragma unroll
        for (int nt = 0; nt < 4; nt++) {
            const int r0 = m0 + wm + mt * 16 + (lane >> 2);
            const int col = n0 + wn + nt * 8 + (lane & 3) * 2;
            if (EPI) {
                float* C = (float*)Cout;
                if (r0 < CC) {
                    const size_t o0 = (size_t)r0 * SPATIAL + col;
                    const float bb = bias[r0];
                    const float2 x0 = *(const float2*)(R + o0);
                    *(float2*)(C + o0) = make_float2(c[mt][nt][0] + bb + x0.x,
                                                     c[mt][nt][1] + bb + x0.y);
                }
                if (r0 + 8 < CC) {
                    const size_t o1 = (size_t)(r0 + 8) * SPATIAL + col;
                    const float bb = bias[r0 + 8];
                    const float2 x1 = *(const float2*)(R + o1);
                    *(float2*)(C + o1) = make_float2(c[mt][nt][2] + bb + x1.x,
                                                     c[mt][nt][3] + bb + x1.y);
                }
            } else {
                __half* C = (__half*)Cout;
                if (r0 < CC) {
                    *(__half2*)(C + (size_t)r0 * SPATIAL + col) =
                        __floats2half2_rn(c[mt][nt][0], c[mt][nt][1]);
                }
                if (r0 + 8 < CC) {
                    *(__half2*)(C + (size_t)(r0 + 8) * SPATIAL + col) =
                        __floats2half2_rn(c[mt][nt][2], c[mt][nt][3]);
                }
            }
        }
    }
}

__global__ __launch_bounds__(256, 2) void qkv_tc(
    const __half* __restrict__ Wh, const __half* __restrict__ Xh,
    __half* __restrict__ out)
{
    const int slab = blockIdx.z;
    const int wsel = blockIdx.y / 3, mt = blockIdx.y % 3;
    tc_gemm<false>(Wh + (size_t)wsel * CC * CC, Xh + (size_t)slab * SLAB,
                   out + (size_t)wsel * NELEM + (size_t)slab * SLAB,
                   nullptr, nullptr, mt * 128, blockIdx.x * 128);
}

__global__ __launch_bounds__(256, 2) void o_tc(
    const __half* __restrict__ Wh, const __half* __restrict__ O,
    const float* __restrict__ bo, const float* __restrict__ X,
    float* __restrict__ out)
{
    const int slab = blockIdx.z;
    tc_gemm<true>(Wh + 3ull * CC * CC, O + (size_t)slab * SLAB,
                  out + (size_t)slab * SLAB, bo, X + (size_t)slab * SLAB,
                  blockIdx.y * 128, blockIdx.x * 128);
}

// ================= Attention (fp16 I/O, fp32 math) =================
// Block = (b, h, 32 spatial). 256 thr; warp tg does t=tg then t=15-tg.
// K,V staged in smem as fp16 (81920B) + rel tables fp32 -> 92.5KB, 2 CTA/SM.
__global__ __launch_bounds__(256, 2) void attn_kernel(
    const __half* __restrict__ Qg, const __half* __restrict__ Kg,
    const __half* __restrict__ Vg, __half* __restrict__ Og,
    const float* __restrict__ relk, const float* __restrict__ relv)
{
    extern __shared__ char smc[];
    __half* Ks = (__half*)smc;                   // 16*40*32 = 20480 halves
    __half* Vs = Ks + TT * DH * 32;              // 20480 halves
    float* Rk = (float*)(Vs + TT * DH * 32);     // 1320
    float* Rv = Rk + 33 * DH;                    // 1320

    const int b = blockIdx.z;
    const int h = blockIdx.y;
    const int s0 = blockIdx.x * 32;
    const int tid = threadIdx.x;

    // stage K,V as half2 (coalesced)
    for (int i = tid; i < TT * DH * 16; i += 256) {
        const int row = i >> 4, pr = i & 15;
        const int f = row / DH, dd = row - f * DH;
        const size_t g =
            ((size_t)((b * TT + f) * CC + h * DH + dd)) * SPATIAL + s0 + pr * 2;
        *(__half2*)(Ks + row * 32 + pr * 2) = *(const __half2*)(Kg + g);
        *(__half2*)(Vs + row * 32 + pr * 2) = *(const __half2*)(Vg + g);
    }
    for (int i = tid; i < 33 * DH; i += 256) {
        Rk[i] = relk[i];
        Rv[i] = relv[i];
    }
    __syncthreads();

    const int sl = tid & 31;
    const int tg = tid >> 5;
    const float scale = 0.15811388300841898f;  // 40^-0.5

    for (int rep = 0; rep < 2; rep++) {
        const int t = rep ? (15 - tg) : tg;    // warp-uniform
        const size_t base =
            ((size_t)((b * TT + t) * CC + h * DH)) * SPATIAL + s0 + sl;

        float q[DH];
#pragma unroll
        for (int dd = 0; dd < DH; dd++)
            q[dd] = __half2float(Qg[base + (size_t)dd * SPATIAL]);

        float sim[TT];
        float mx = -1e30f;
#pragma unroll
        for (int sp = 0; sp < TT; sp++) {
            if (sp > t) break;                 // warp-uniform
            const __half* kp = Ks + (sp * DH) * 32 + sl;
            const float* rp = Rk + (sp - t + TT) * DH;
            float acc = 0.f;
#pragma unroll
            for (int dd = 0; dd < DH; dd++)
                acc += q[dd] * (__half2float(kp[dd * 32]) + rp[dd]);
            acc *= scale;
            sim[sp] = acc;
            mx = fmaxf(mx, acc);
        }
        float den = 0.f;
#pragma unroll
        for (int sp = 0; sp < TT; sp++) {
            if (sp > t) break;
            const float e = __expf(sim[sp] - mx);
            sim[sp] = e;
            den += e;
        }
        const float inv = 1.f / den;

        float o[DH];
#pragma unroll
        for (int dd = 0; dd < DH; dd++) o[dd] = 0.f;
#pragma unroll
        for (int sp = 0; sp < TT; sp++) {
            if (sp > t) break;
            const float a = sim[sp];
            const __half* vp = Vs + (sp * DH) * 32 + sl;
            const float* rp = Rv + (sp - t + TT) * DH;
#pragma unroll
            for (int dd = 0; dd < DH; dd++)
                o[dd] += a * (__half2float(vp[dd * 32]) + rp[dd]);
        }
#pragma unroll
        for (int dd = 0; dd < DH; dd++)
            Og[base + (size_t)dd * SPATIAL] = __float2half_rn(o[dd] * inv);
    }
}

// ================= launch =================
extern "C" void kernel_launch(void* const* d_in, const int* in_sizes, int n_in,
                              void* d_out, int out_size) {
    const float* x  = (const float*)d_in[0];
    const float* Wq = (const float*)d_in[1];
    const float* Wk = (const float*)d_in[2];
    const float* Wv = (const float*)d_in[3];
    const float* Wo = (const float*)d_in[4];
    const float* bo = (const float*)d_in[5];
    const float* rk = (const float*)d_in[6];
    const float* rv = (const float*)d_in[7];
    float* out = (float*)d_out;

    __half* hb = nullptr;
    cudaGetSymbolAddress((void**)&hb, g_hbuf);
    __half* Q  = hb;
    __half* K  = hb + 1ull * NELEM;
    __half* V  = hb + 2ull * NELEM;
    __half* O  = hb + 3ull * NELEM;
    __half* Xh = hb + 4ull * NELEM;
    __half* Wh = hb + 5ull * NELEM;

    cvt_w<<<dim3(100, 4), 1024>>>(Wq, Wk, Wv, Wo, Wh);
    cvt_x<<<(unsigned)(NELEM / (256 * 8)), 256>>>(x, Xh);

    const int gsm = 3 * STAGEB;  // 56832
    cudaFuncSetAttribute((const void*)qkv_tc,
                         cudaFuncAttributeMaxDynamicSharedMemorySize, gsm);
    cudaFuncSetAttribute((const void*)o_tc,
                         cudaFuncAttributeMaxDynamicSharedMemorySize, gsm);

    qkv_tc<<<dim3(SPATIAL / 128, 9, NSLAB), 256, gsm>>>(Wh, Xh, hb);

    const int asmb = (TT * DH * 32 * 2) * 2 + 2 * 33 * DH * 4;  // 92480
    cudaFuncSetAttribute((const void*)attn_kernel,
                         cudaFuncAttributeMaxDynamicSharedMemorySize, asmb);
    attn_kernel<<<dim3(SPATIAL / 32, HEADS, 4), 256, asmb>>>(Q, K, V, O, rk, rv);

    o_tc<<<dim3(SPATIAL / 128, 3, NSLAB), 256, gsm>>>(Wh, O, bo, x, out);
}